// round 5
// baseline (speedup 1.0000x reference)
#include <cuda_runtime.h>
#include <cuda_bf16.h>
#include <math.h>
#include <stdint.h>

// ---------------------------------------------------------------------------
// Problem constants
// ---------------------------------------------------------------------------
#define CHAR_SIZE 128
#define CE        64
#define HE        128      // char LSTM hidden
#define WE        256
#define HP        256      // word LSTM hidden
#define TAGS      50
#define NWORDS    8192
#define MAXCH     16
#define G_E       (4*HE)   // 512
#define G_P       (4*HP)   // 1024
#define KIN_P     (WE+HE)  // 384

// ---------------------------------------------------------------------------
// Scratch (static device globals; no allocation allowed)
// ---------------------------------------------------------------------------
__device__ float g_tablep[CHAR_SIZE * G_E];      // [ch][u*4+q] char xgate table (+biases)
__device__ float g_WTe[HE * G_E];                // [k][u*4+q]  permuted Whh_e
__device__ float g_WpT[KIN_P * G_P];             // [k][g]      transposed Wih_p
__device__ float g_xg[(size_t)NWORDS * G_P];     // word-LSTM input gates (+biases)
__device__ float g_hchar[NWORDS * HE];           // char LSTM final hidden
__device__ float g_hs[NWORDS * HP];              // word LSTM hidden states

// ---------------------------------------------------------------------------
// Packed f32x2 helpers (Blackwell: fma.rn.f32x2 only reachable via PTX)
// ---------------------------------------------------------------------------
#define FMA_F32X2(acc, a, b) \
    asm("fma.rn.f32x2 %0, %1, %2, %0;" : "+l"(acc) : "l"(a), "l"(b))
#define SPLAT_F32X2(out, f) \
    asm("mov.b64 %0, {%1, %1};" : "=l"(out) : "f"(f))
#define UNPACK_F32X2(lo, hi, v) \
    asm("mov.b64 {%0, %1}, %2;" : "=f"(lo), "=f"(hi) : "l"(v))

// ---------------------------------------------------------------------------
// Fast activations
// ---------------------------------------------------------------------------
__device__ __forceinline__ float sigf(float x) {
    return __fdividef(1.0f, 1.0f + __expf(-x));
}
__device__ __forceinline__ float tanhfast(float x) {
    x = fminf(9.0f, fmaxf(-9.0f, x));
    float e = __expf(-2.0f * x);
    return __fdividef(1.0f - e, 1.0f + e);
}

// ---------------------------------------------------------------------------
// Prep kernels
// ---------------------------------------------------------------------------
__global__ void prep_table_kernel(const float* __restrict__ char_emb,
                                  const float* __restrict__ Wih_e,
                                  const float* __restrict__ bih_e,
                                  const float* __restrict__ bhh_e) {
    int idx = blockIdx.x * 256 + threadIdx.x;        // 0 .. 128*512-1
    int ch = idx >> 9;
    int col = idx & 511;
    int u = col >> 2, q = col & 3;
    int row = q * HE + u;
    float acc = bih_e[row] + bhh_e[row];
    const float* ce = char_emb + ch * CE;
    const float* wr = Wih_e + row * CE;
#pragma unroll 16
    for (int k = 0; k < CE; k++) acc = fmaf(ce[k], wr[k], acc);
    g_tablep[idx] = acc;
}

__global__ void prep_wte_kernel(const float* __restrict__ Whh_e) {
    int idx = blockIdx.x * 256 + threadIdx.x;
    int k = idx >> 9;
    int col = idx & 511;
    int u = col >> 2, q = col & 3;
    g_WTe[idx] = Whh_e[(q * HE + u) * HE + k];
}

__global__ void prep_wpt_kernel(const float* __restrict__ Wih_p) {
    int idx = blockIdx.x * 256 + threadIdx.x;
    int k = idx >> 10;
    int g = idx & 1023;
    g_WpT[idx] = Wih_p[g * KIN_P + k];
}

// ---------------------------------------------------------------------------
// Char LSTM: 128 blocks x 256 threads, 64 words per block, f32x2 GEMM.
// (unchanged this round; word kernel is the experiment)
// ---------------------------------------------------------------------------
#define CHAR_SMEM_BYTES ((4 * HE * 64 + 128) * 4)

__global__ void __launch_bounds__(256, 1)
char_lstm_kernel(const int* __restrict__ char_ids,
                 const int* __restrict__ char_lengths) {
    extern __shared__ __align__(16) float sm[];
    float* hA = sm;                        // [128][64]
    float* hB = sm + 8192;                 // [128][64]
    float* cT = sm + 16384;                // [128][64]
    float* wt = sm + 24576;                // [128][64]
    int*   lens = (int*)(sm + 32768);      // [64]
    int*   chs  = (int*)(sm + 32768 + 64); // [64]

    int tid = threadIdx.x;
    int wbase = blockIdx.x * 64;

    for (int i = tid; i < 8192; i += 256) { hA[i] = 0.0f; cT[i] = 0.0f; }
    if (tid < 64) lens[tid] = char_lengths[wbase + tid];
    __syncthreads();

    int w0 = (tid >> 4) << 2;   // word base (0..60)
    int ug = tid & 15;          // unit-in-tile
    int c0 = ug << 2;           // column base in weight tile

    for (int t = 0; t < MAXCH; t++) {
        if (tid < 64) chs[tid] = char_ids[(wbase + tid) * MAXCH + t];
        float* hc = (t & 1) ? hB : hA;
        float* hn = (t & 1) ? hA : hB;

        for (int uc = 0; uc < 8; uc++) {
#pragma unroll
            for (int j = 0; j < 8; j++) {
                int lin = tid + 256 * j;             // 0..2047 float4 slots
                int k = lin >> 4;
                int c4 = lin & 15;
                float4 v = *(const float4*)(g_WTe + k * G_E + uc * 64 + c4 * 4);
                *((float4*)(wt + k * 64 + c4 * 4)) = v;
            }
            __syncthreads();

            unsigned long long acc2[2][4];
#pragma unroll
            for (int a = 0; a < 2; a++)
#pragma unroll
                for (int b = 0; b < 4; b++) acc2[a][b] = 0ull;

#pragma unroll 4
            for (int k = 0; k < HE; k++) {
                float4 b = *(const float4*)(wt + k * 64 + c0);
                ulonglong2 av = *(const ulonglong2*)(hc + k * 64 + w0);
                unsigned long long bx, by, bz, bw;
                SPLAT_F32X2(bx, b.x);
                SPLAT_F32X2(by, b.y);
                SPLAT_F32X2(bz, b.z);
                SPLAT_F32X2(bw, b.w);
                FMA_F32X2(acc2[0][0], av.x, bx);
                FMA_F32X2(acc2[0][1], av.x, by);
                FMA_F32X2(acc2[0][2], av.x, bz);
                FMA_F32X2(acc2[0][3], av.x, bw);
                FMA_F32X2(acc2[1][0], av.y, bx);
                FMA_F32X2(acc2[1][1], av.y, by);
                FMA_F32X2(acc2[1][2], av.y, bz);
                FMA_F32X2(acc2[1][3], av.y, bw);
            }

            float accf[4][4];
#pragma unroll
            for (int rp = 0; rp < 2; rp++)
#pragma unroll
                for (int cx = 0; cx < 4; cx++)
                    UNPACK_F32X2(accf[2 * rp][cx], accf[2 * rp + 1][cx], acc2[rp][cx]);

            int u = uc * 16 + ug;
#pragma unroll
            for (int j = 0; j < 4; j++) {
                int w = w0 + j;
                int ch = chs[w];
                float4 tb = *(const float4*)(g_tablep + ch * G_E + u * 4);
                float pi = accf[j][0] + tb.x;
                float pf = accf[j][1] + tb.y;
                float pg = accf[j][2] + tb.z;
                float po = accf[j][3] + tb.w;
                float iv = sigf(pi), fv = sigf(pf);
                float gv = tanhfast(pg), ov = sigf(po);
                float cold = cT[u * 64 + w];
                float hold = hc[u * 64 + w];
                float cn = fmaf(fv, cold, iv * gv);
                float hh = ov * tanhfast(cn);
                bool msk = (t < lens[w]);
                hn[u * 64 + w] = msk ? hh : hold;
                cT[u * 64 + w] = msk ? cn : cold;
            }
            __syncthreads();
        }
    }
    for (int lin = tid; lin < 8192; lin += 256) {
        int u = lin & 127;
        int w = lin >> 7;
        g_hchar[(wbase + w) * HE + u] = hA[u * 64 + w];
    }
}

// ---------------------------------------------------------------------------
// Word-LSTM input gates: xg[n][g] = feats[n] @ Wih_p.T + bih_p + bhh_p
// ---------------------------------------------------------------------------
__global__ void __launch_bounds__(256)
xgates_kernel(const float* __restrict__ word_emb,
              const int* __restrict__ sentence,
              const float* __restrict__ bih_p,
              const float* __restrict__ bhh_p) {
    __shared__ float As[64 * 65];
    __shared__ float Bs[64 * 64];
    __shared__ int   sent[64];

    int bg = blockIdx.x;   // 0..15
    int bn = blockIdx.y;   // 0..127
    int tid = threadIdx.x;
    if (tid < 64) sent[tid] = sentence[bn * 64 + tid];

    int n0 = (tid >> 4) << 2;
    int g0 = (tid & 15) << 2;

    float acc[4][4];
#pragma unroll
    for (int a = 0; a < 4; a++)
#pragma unroll
        for (int b = 0; b < 4; b++) acc[a][b] = 0.0f;

    for (int kc = 0; kc < 6; kc++) {
        __syncthreads();
#pragma unroll
        for (int j = 0; j < 16; j++) {
            int lin = tid + 256 * j;                 // 0..4095
            int nn = lin >> 6;
            int k = lin & 63;
            int kk = kc * 64 + k;
            float v;
            if (kk < WE) v = word_emb[(size_t)sent[nn] * WE + kk];
            else         v = g_hchar[(bn * 64 + nn) * HE + (kk - WE)];
            As[nn * 65 + k] = v;
            Bs[nn * 64 + k] = g_WpT[(size_t)(kc * 64 + nn) * G_P + bg * 64 + k];
        }
        __syncthreads();
#pragma unroll 4
        for (int k = 0; k < 64; k++) {
            float4 b = *(const float4*)(Bs + k * 64 + g0);
            float a0 = As[(n0 + 0) * 65 + k];
            float a1 = As[(n0 + 1) * 65 + k];
            float a2 = As[(n0 + 2) * 65 + k];
            float a3 = As[(n0 + 3) * 65 + k];
            acc[0][0] = fmaf(a0, b.x, acc[0][0]);
            acc[0][1] = fmaf(a0, b.y, acc[0][1]);
            acc[0][2] = fmaf(a0, b.z, acc[0][2]);
            acc[0][3] = fmaf(a0, b.w, acc[0][3]);
            acc[1][0] = fmaf(a1, b.x, acc[1][0]);
            acc[1][1] = fmaf(a1, b.y, acc[1][1]);
            acc[1][2] = fmaf(a1, b.z, acc[1][2]);
            acc[1][3] = fmaf(a1, b.w, acc[1][3]);
            acc[2][0] = fmaf(a2, b.x, acc[2][0]);
            acc[2][1] = fmaf(a2, b.y, acc[2][1]);
            acc[2][2] = fmaf(a2, b.z, acc[2][2]);
            acc[2][3] = fmaf(a2, b.w, acc[2][3]);
            acc[3][0] = fmaf(a3, b.x, acc[3][0]);
            acc[3][1] = fmaf(a3, b.y, acc[3][1]);
            acc[3][2] = fmaf(a3, b.z, acc[3][2]);
            acc[3][3] = fmaf(a3, b.w, acc[3][3]);
        }
    }

    int ggl = bg * 64 + g0;
    float4 bi = *(const float4*)(bih_p + ggl);
    float4 bh = *(const float4*)(bhh_p + ggl);
#pragma unroll
    for (int l = 0; l < 4; l++) {
        float4 o;
        o.x = acc[l][0] + bi.x + bh.x;
        o.y = acc[l][1] + bi.y + bh.y;
        o.z = acc[l][2] + bi.z + bh.z;
        o.w = acc[l][3] + bi.w + bh.w;
        *(float4*)(g_xg + (size_t)(bn * 64 + n0 + l) * G_P + ggl) = o;
    }
}

// ---------------------------------------------------------------------------
// Word LSTM: 8-CTA cluster, packed f32x2 matvec, cp.async.bulk h-broadcast.
// Warp w: gate q=w&3, k-slice ks=w>>2; lane = unit within CTA.
// CTA r owns hidden units [r*32, r*32+32). Tail/orchestration in warp 15
// (highest wid -> highest arbiter priority).
// ---------------------------------------------------------------------------
__device__ __forceinline__ uint32_t cluster_rank_() {
    uint32_t r;
    asm("mov.u32 %0, %%cluster_ctarank;" : "=r"(r));
    return r;
}
__device__ __forceinline__ void cluster_sync_() {
    asm volatile("barrier.cluster.arrive.aligned;" ::: "memory");
    asm volatile("barrier.cluster.wait.aligned;" ::: "memory");
}
__device__ __forceinline__ uint32_t mapa_u32(uint32_t la, int r) {
    uint32_t ra;
    asm("mapa.shared::cluster.u32 %0, %1, %2;" : "=r"(ra) : "r"(la), "r"(r));
    return ra;
}
__device__ __forceinline__ void mbar_init_(uint32_t bar, uint32_t cnt) {
    asm volatile("mbarrier.init.shared.b64 [%0], %1;" :: "r"(bar), "r"(cnt) : "memory");
}
__device__ __forceinline__ void mbar_arrive_expect_(uint32_t bar, uint32_t bytes) {
    asm volatile("mbarrier.arrive.expect_tx.shared.b64 _, [%0], %1;"
                 :: "r"(bar), "r"(bytes) : "memory");
}
__device__ __forceinline__ void mbar_wait_parity_(uint32_t bar, uint32_t ph) {
    asm volatile(
        "{\n\t"
        ".reg .pred P1;\n\t"
        "WL_%=:\n\t"
        "mbarrier.try_wait.parity.acquire.cluster.shared::cta.b64 P1, [%0], %1, 0x989680;\n\t"
        "@P1 bra.uni WD_%=;\n\t"
        "bra.uni WL_%=;\n\t"
        "WD_%=:\n\t"
        "}"
        :: "r"(bar), "r"(ph) : "memory");
}
__device__ __forceinline__ void fence_proxy_async_cta_() {
    asm volatile("fence.proxy.async.shared::cta;" ::: "memory");
}
// 128B smem->remote-smem bulk copy; complete_tx on the RECEIVER's mbarrier.
__device__ __forceinline__ void bulk_s2s_(uint32_t dst_cluster, uint32_t src_cta,
                                          uint32_t bytes, uint32_t mbar_cluster) {
    asm volatile(
        "cp.async.bulk.shared::cluster.shared::cta.mbarrier::complete_tx::bytes "
        "[%0], [%1], %2, [%3];"
        :: "r"(dst_cluster), "r"(src_cta), "r"(bytes), "r"(mbar_cluster) : "memory");
}

__global__ void __launch_bounds__(512, 1) __cluster_dims__(8, 1, 1)
word_lstm_kernel(const float* __restrict__ Whh_p) {
    __shared__ __align__(16) float hbuf[2][HP];     // h double-buffer (per-CTA replica)
    __shared__ __align__(16) float stg[2][32];      // bulk-copy source, parity-buffered
    __shared__ float pacc[512];
    __shared__ __align__(8) unsigned long long hbar[2];

    int rank = (int)cluster_rank_();
    int tid = threadIdx.x;
    int w = tid >> 5, lane = tid & 31;
    int q = w & 3;                        // gate quadrant
    int ks = w >> 2;                      // k-slice 0..3
    int grow = q * HP + rank * 32 + lane; // global gate row 0..1023

    // resident packed weights: Whh_p[grow][ks*64 .. ks*64+64) as 32 f32x2
    unsigned long long wreg[32];
    {
        const float* wp = Whh_p + (size_t)grow * HP + ks * 64;
#pragma unroll
        for (int i = 0; i < 16; i++) {
            ulonglong2 v = *(const ulonglong2*)(wp + i * 4);
            wreg[2 * i] = v.x;
            wreg[2 * i + 1] = v.y;
        }
    }

    ((float*)hbuf)[tid] = 0.0f;           // 512 floats = both buffers
    uint32_t bar0 = (uint32_t)__cvta_generic_to_shared(&hbar[0]);
    uint32_t hb0  = (uint32_t)__cvta_generic_to_shared(&hbuf[0][0]);
    uint32_t st0  = (uint32_t)__cvta_generic_to_shared(&stg[0][0]);
    if (tid == 0) { mbar_init_(bar0, 1); mbar_init_(bar0 + 8, 1); }

    // hoisted remote addresses (barrier[0] and hbuf[0] bases per peer)
    uint32_t rd_h[8], rd_b[8];
#pragma unroll
    for (int r = 0; r < 8; r++) {
        rd_h[r] = mapa_u32(hb0, r);
        rd_b[r] = mapa_u32(bar0, r);
    }

    bool tail = (w == 15);
    float c = 0.0f;
    float xc0 = 0.f, xc1 = 0.f, xc2 = 0.f, xc3 = 0.f;
    if (tail) {
        const float* xp = g_xg + rank * 32 + lane;
        xc0 = __ldg(xp);
        xc1 = __ldg(xp + HP);
        xc2 = __ldg(xp + 2 * HP);
        xc3 = __ldg(xp + 3 * HP);
    }
    __syncthreads();
    cluster_sync_();   // barriers + hbuf init visible cluster-wide

    for (int n = 0; n < NWORDS; n++) {
        int p = n & 1;
        if (n > 0)   // wait for h_n delivery (completion n-1 on barrier[(n-1)&1])
            mbar_wait_parity_(bar0 + ((n - 1) & 1) * 8, (uint32_t)(((n - 1) >> 1) & 1));
        if (tid == 0 && n < NWORDS - 1)
            mbar_arrive_expect_(bar0 + p * 8, 1024u);   // 8 peers * 128B

        // prefetch next-step input gates (tail warp; consumed next iteration)
        float xn0 = 0.f, xn1 = 0.f, xn2 = 0.f, xn3 = 0.f;
        if (tail && n + 1 < NWORDS) {
            const float* xp = g_xg + (size_t)(n + 1) * G_P + rank * 32 + lane;
            xn0 = __ldg(xp);
            xn1 = __ldg(xp + HP);
            xn2 = __ldg(xp + 2 * HP);
            xn3 = __ldg(xp + 3 * HP);
        }

        // packed matvec slice: lane-uniform smem reads (broadcast)
        const ulonglong2* hp2 = (const ulonglong2*)(&hbuf[p][ks * 64]);
        unsigned long long a0 = 0ull, a1 = 0ull;
#pragma unroll
        for (int i = 0; i < 16; i++) {
            ulonglong2 hv = hp2[i];
            FMA_F32X2(a0, wreg[2 * i], hv.x);
            FMA_F32X2(a1, wreg[2 * i + 1], hv.y);
        }
        {
            float l0, h0, l1, h1;
            UNPACK_F32X2(l0, h0, a0);
            UNPACK_F32X2(l1, h1, a1);
            pacc[tid] = (l0 + h0) + (l1 + h1);
        }
        __syncthreads();

        if (tail) {
            // lane = unit; gather 4 k-slices per gate (stride-128, bank = lane)
            float s0 = 0.f, s1 = 0.f, s2 = 0.f, s3 = 0.f;
#pragma unroll
            for (int k2 = 0; k2 < 4; k2++) {
                int base = k2 * 128 + lane;
                s0 += pacc[base];
                s1 += pacc[base + 32];
                s2 += pacc[base + 64];
                s3 += pacc[base + 96];
            }
            float iv = sigf(s0 + xc0);
            float fv = sigf(s1 + xc1);
            float gv = tanhfast(s2 + xc2);
            float ov = sigf(s3 + xc3);
            c = fmaf(fv, c, iv * gv);
            float hn = ov * tanhfast(c);
            g_hs[(size_t)n * HP + rank * 32 + lane] = hn;

            if (n < NWORDS - 1) {
                stg[p][lane] = hn;                    // stage 32 floats = 128B
                __syncwarp();
                fence_proxy_async_cta_();             // STS -> async proxy visible
                if (lane < 8) {
                    uint32_t dst = rd_h[lane] + (uint32_t)((p ^ 1) * (HP * 4) + rank * 128);
                    uint32_t mb  = rd_b[lane] + (uint32_t)(p * 8);
                    bulk_s2s_(dst, st0 + (uint32_t)(p * 128), 128u, mb);
                }
            }
            xc0 = xn0; xc1 = xn1; xc2 = xn2; xc3 = xn3;
        }
    }
    cluster_sync_();   // no CTA exits while peers' bulk copies may be in flight
}

// ---------------------------------------------------------------------------
// Tag projection + log-softmax: one block (64 threads) per word
// ---------------------------------------------------------------------------
__global__ void __launch_bounds__(64)
tag_kernel(const float* __restrict__ W_tag,
           const float* __restrict__ b_tag,
           float* __restrict__ out) {
    __shared__ float hs[HP];
    __shared__ float vals[TAGS];
    __shared__ float red[2];

    int n = blockIdx.x;
    int t = threadIdx.x;
    *(float4*)(hs + t * 4) = *(const float4*)(g_hs + (size_t)n * HP + t * 4);
    __syncthreads();

    if (t < TAGS) {
        const float* wr = W_tag + t * HP;
        float a0 = b_tag[t], a1 = 0.0f, a2 = 0.0f, a3 = 0.0f;
#pragma unroll 8
        for (int k = 0; k < HP; k += 4) {
            float4 wv = *(const float4*)(wr + k);
            a0 = fmaf(wv.x, hs[k + 0], a0);
            a1 = fmaf(wv.y, hs[k + 1], a1);
            a2 = fmaf(wv.z, hs[k + 2], a2);
            a3 = fmaf(wv.w, hs[k + 3], a3);
        }
        vals[t] = (a0 + a1) + (a2 + a3);
    }
    __syncthreads();

    if (t < 32) {
        float m = vals[t];
        if (t + 32 < TAGS) m = fmaxf(m, vals[t + 32]);
#pragma unroll
        for (int o = 16; o > 0; o >>= 1)
            m = fmaxf(m, __shfl_xor_sync(0xffffffffu, m, o));
        float s = expf(vals[t] - m);
        if (t + 32 < TAGS) s += expf(vals[t + 32] - m);
#pragma unroll
        for (int o = 16; o > 0; o >>= 1)
            s += __shfl_xor_sync(0xffffffffu, s, o);
        if (t == 0) { red[0] = m; red[1] = logf(s); }
    }
    __syncthreads();

    if (t < TAGS) out[(size_t)n * TAGS + t] = vals[t] - red[0] - red[1];
}

// ---------------------------------------------------------------------------
// Launch
// ---------------------------------------------------------------------------
extern "C" void kernel_launch(void* const* d_in, const int* in_sizes, int n_in,
                              void* d_out, int out_size) {
    const float* char_emb = (const float*)d_in[0];
    const float* word_emb = (const float*)d_in[1];
    const float* Wih_e    = (const float*)d_in[2];
    const float* Whh_e    = (const float*)d_in[3];
    const float* bih_e    = (const float*)d_in[4];
    const float* bhh_e    = (const float*)d_in[5];
    const float* Wih_p    = (const float*)d_in[6];
    const float* Whh_p    = (const float*)d_in[7];
    const float* bih_p    = (const float*)d_in[8];
    const float* bhh_p    = (const float*)d_in[9];
    const float* W_tag    = (const float*)d_in[10];
    const float* b_tag    = (const float*)d_in[11];
    const int*   sentence = (const int*)d_in[12];
    const int*   char_ids = (const int*)d_in[13];
    const int*   char_len = (const int*)d_in[14];
    float* out = (float*)d_out;

    (void)in_sizes; (void)n_in; (void)out_size;

    cudaFuncSetAttribute(char_lstm_kernel,
                         cudaFuncAttributeMaxDynamicSharedMemorySize,
                         CHAR_SMEM_BYTES);

    prep_table_kernel<<<256, 256>>>(char_emb, Wih_e, bih_e, bhh_e);
    prep_wte_kernel<<<256, 256>>>(Whh_e);
    prep_wpt_kernel<<<1536, 256>>>(Wih_p);

    char_lstm_kernel<<<128, 256, CHAR_SMEM_BYTES>>>(char_ids, char_len);

    xgates_kernel<<<dim3(16, 128), 256>>>(word_emb, sentence, bih_p, bhh_p);

    word_lstm_kernel<<<8, 512>>>(Whh_p);

    tag_kernel<<<NWORDS, 64>>>(W_tag, b_tag, out);
}

// round 6
// speedup vs baseline: 1.3795x; 1.3795x over previous
#include <cuda_runtime.h>
#include <cuda_bf16.h>
#include <math.h>
#include <stdint.h>

// ---------------------------------------------------------------------------
// Problem constants
// ---------------------------------------------------------------------------
#define CHAR_SIZE 128
#define CE        64
#define HE        128      // char LSTM hidden
#define WE        256
#define HP        256      // word LSTM hidden
#define TAGS      50
#define NWORDS    8192
#define MAXCH     16
#define G_E       (4*HE)   // 512
#define G_P       (4*HP)   // 1024
#define KIN_P     (WE+HE)  // 384

// ---------------------------------------------------------------------------
// Scratch (static device globals; no allocation allowed)
// ---------------------------------------------------------------------------
__device__ float g_tablep[CHAR_SIZE * G_E];      // [ch][u*4+q] char xgate table (+biases)
__device__ float g_WTe[HE * G_E];                // [k][u*4+q]  permuted Whh_e
__device__ float g_WpT[KIN_P * G_P];             // [k][g]      transposed Wih_p
__device__ float g_xg[(size_t)NWORDS * G_P];     // word-LSTM input gates (+biases)
__device__ float g_hchar[NWORDS * HE];           // char LSTM final hidden
__device__ float g_hs[NWORDS * HP];              // word LSTM hidden states

// ---------------------------------------------------------------------------
// Packed f32x2 helpers (Blackwell: fma.rn.f32x2 only reachable via PTX)
// ---------------------------------------------------------------------------
#define FMA_F32X2(acc, a, b) \
    asm("fma.rn.f32x2 %0, %1, %2, %0;" : "+l"(acc) : "l"(a), "l"(b))
#define SPLAT_F32X2(out, f) \
    asm("mov.b64 %0, {%1, %1};" : "=l"(out) : "f"(f))
#define UNPACK_F32X2(lo, hi, v) \
    asm("mov.b64 {%0, %1}, %2;" : "=f"(lo), "=f"(hi) : "l"(v))

// ---------------------------------------------------------------------------
// Fast activations
// ---------------------------------------------------------------------------
__device__ __forceinline__ float sigf(float x) {
    return __fdividef(1.0f, 1.0f + __expf(-x));
}
__device__ __forceinline__ float tanhfast(float x) {
    x = fminf(9.0f, fmaxf(-9.0f, x));
    float e = __expf(-2.0f * x);
    return __fdividef(1.0f - e, 1.0f + e);
}

// ---------------------------------------------------------------------------
// Prep kernels
// ---------------------------------------------------------------------------
__global__ void prep_table_kernel(const float* __restrict__ char_emb,
                                  const float* __restrict__ Wih_e,
                                  const float* __restrict__ bih_e,
                                  const float* __restrict__ bhh_e) {
    int idx = blockIdx.x * 256 + threadIdx.x;        // 0 .. 128*512-1
    int ch = idx >> 9;
    int col = idx & 511;
    int u = col >> 2, q = col & 3;
    int row = q * HE + u;
    float acc = bih_e[row] + bhh_e[row];
    const float* ce = char_emb + ch * CE;
    const float* wr = Wih_e + row * CE;
#pragma unroll 16
    for (int k = 0; k < CE; k++) acc = fmaf(ce[k], wr[k], acc);
    g_tablep[idx] = acc;
}

__global__ void prep_wte_kernel(const float* __restrict__ Whh_e) {
    int idx = blockIdx.x * 256 + threadIdx.x;
    int k = idx >> 9;
    int col = idx & 511;
    int u = col >> 2, q = col & 3;
    g_WTe[idx] = Whh_e[(q * HE + u) * HE + k];
}

__global__ void prep_wpt_kernel(const float* __restrict__ Wih_p) {
    int idx = blockIdx.x * 256 + threadIdx.x;
    int k = idx >> 10;
    int g = idx & 1023;
    g_WpT[idx] = Wih_p[g * KIN_P + k];
}

// ---------------------------------------------------------------------------
// Char LSTM: 128 blocks x 256 threads, 64 words per block, f32x2 GEMM.
// (unchanged; word kernel is this round's experiment)
// ---------------------------------------------------------------------------
#define CHAR_SMEM_BYTES ((4 * HE * 64 + 128) * 4)

__global__ void __launch_bounds__(256, 1)
char_lstm_kernel(const int* __restrict__ char_ids,
                 const int* __restrict__ char_lengths) {
    extern __shared__ __align__(16) float sm[];
    float* hA = sm;                        // [128][64]
    float* hB = sm + 8192;                 // [128][64]
    float* cT = sm + 16384;                // [128][64]
    float* wt = sm + 24576;                // [128][64]
    int*   lens = (int*)(sm + 32768);      // [64]
    int*   chs  = (int*)(sm + 32768 + 64); // [64]

    int tid = threadIdx.x;
    int wbase = blockIdx.x * 64;

    for (int i = tid; i < 8192; i += 256) { hA[i] = 0.0f; cT[i] = 0.0f; }
    if (tid < 64) lens[tid] = char_lengths[wbase + tid];
    __syncthreads();

    int w0 = (tid >> 4) << 2;   // word base (0..60)
    int ug = tid & 15;          // unit-in-tile
    int c0 = ug << 2;           // column base in weight tile

    for (int t = 0; t < MAXCH; t++) {
        if (tid < 64) chs[tid] = char_ids[(wbase + tid) * MAXCH + t];
        float* hc = (t & 1) ? hB : hA;
        float* hn = (t & 1) ? hA : hB;

        for (int uc = 0; uc < 8; uc++) {
#pragma unroll
            for (int j = 0; j < 8; j++) {
                int lin = tid + 256 * j;             // 0..2047 float4 slots
                int k = lin >> 4;
                int c4 = lin & 15;
                float4 v = *(const float4*)(g_WTe + k * G_E + uc * 64 + c4 * 4);
                *((float4*)(wt + k * 64 + c4 * 4)) = v;
            }
            __syncthreads();

            unsigned long long acc2[2][4];
#pragma unroll
            for (int a = 0; a < 2; a++)
#pragma unroll
                for (int b = 0; b < 4; b++) acc2[a][b] = 0ull;

#pragma unroll 4
            for (int k = 0; k < HE; k++) {
                float4 b = *(const float4*)(wt + k * 64 + c0);
                ulonglong2 av = *(const ulonglong2*)(hc + k * 64 + w0);
                unsigned long long bx, by, bz, bw;
                SPLAT_F32X2(bx, b.x);
                SPLAT_F32X2(by, b.y);
                SPLAT_F32X2(bz, b.z);
                SPLAT_F32X2(bw, b.w);
                FMA_F32X2(acc2[0][0], av.x, bx);
                FMA_F32X2(acc2[0][1], av.x, by);
                FMA_F32X2(acc2[0][2], av.x, bz);
                FMA_F32X2(acc2[0][3], av.x, bw);
                FMA_F32X2(acc2[1][0], av.y, bx);
                FMA_F32X2(acc2[1][1], av.y, by);
                FMA_F32X2(acc2[1][2], av.y, bz);
                FMA_F32X2(acc2[1][3], av.y, bw);
            }

            float accf[4][4];
#pragma unroll
            for (int rp = 0; rp < 2; rp++)
#pragma unroll
                for (int cx = 0; cx < 4; cx++)
                    UNPACK_F32X2(accf[2 * rp][cx], accf[2 * rp + 1][cx], acc2[rp][cx]);

            int u = uc * 16 + ug;
#pragma unroll
            for (int j = 0; j < 4; j++) {
                int w = w0 + j;
                int ch = chs[w];
                float4 tb = *(const float4*)(g_tablep + ch * G_E + u * 4);
                float pi = accf[j][0] + tb.x;
                float pf = accf[j][1] + tb.y;
                float pg = accf[j][2] + tb.z;
                float po = accf[j][3] + tb.w;
                float iv = sigf(pi), fv = sigf(pf);
                float gv = tanhfast(pg), ov = sigf(po);
                float cold = cT[u * 64 + w];
                float hold = hc[u * 64 + w];
                float cn = fmaf(fv, cold, iv * gv);
                float hh = ov * tanhfast(cn);
                bool msk = (t < lens[w]);
                hn[u * 64 + w] = msk ? hh : hold;
                cT[u * 64 + w] = msk ? cn : cold;
            }
            __syncthreads();
        }
    }
    for (int lin = tid; lin < 8192; lin += 256) {
        int u = lin & 127;
        int w = lin >> 7;
        g_hchar[(wbase + w) * HE + u] = hA[u * 64 + w];
    }
}

// ---------------------------------------------------------------------------
// Word-LSTM input gates: xg[n][g] = feats[n] @ Wih_p.T + bih_p + bhh_p
// ---------------------------------------------------------------------------
__global__ void __launch_bounds__(256)
xgates_kernel(const float* __restrict__ word_emb,
              const int* __restrict__ sentence,
              const float* __restrict__ bih_p,
              const float* __restrict__ bhh_p) {
    __shared__ float As[64 * 65];
    __shared__ float Bs[64 * 64];
    __shared__ int   sent[64];

    int bg = blockIdx.x;   // 0..15
    int bn = blockIdx.y;   // 0..127
    int tid = threadIdx.x;
    if (tid < 64) sent[tid] = sentence[bn * 64 + tid];

    int n0 = (tid >> 4) << 2;
    int g0 = (tid & 15) << 2;

    float acc[4][4];
#pragma unroll
    for (int a = 0; a < 4; a++)
#pragma unroll
        for (int b = 0; b < 4; b++) acc[a][b] = 0.0f;

    for (int kc = 0; kc < 6; kc++) {
        __syncthreads();
#pragma unroll
        for (int j = 0; j < 16; j++) {
            int lin = tid + 256 * j;                 // 0..4095
            int nn = lin >> 6;
            int k = lin & 63;
            int kk = kc * 64 + k;
            float v;
            if (kk < WE) v = word_emb[(size_t)sent[nn] * WE + kk];
            else         v = g_hchar[(bn * 64 + nn) * HE + (kk - WE)];
            As[nn * 65 + k] = v;
            Bs[nn * 64 + k] = g_WpT[(size_t)(kc * 64 + nn) * G_P + bg * 64 + k];
        }
        __syncthreads();
#pragma unroll 4
        for (int k = 0; k < 64; k++) {
            float4 b = *(const float4*)(Bs + k * 64 + g0);
            float a0 = As[(n0 + 0) * 65 + k];
            float a1 = As[(n0 + 1) * 65 + k];
            float a2 = As[(n0 + 2) * 65 + k];
            float a3 = As[(n0 + 3) * 65 + k];
            acc[0][0] = fmaf(a0, b.x, acc[0][0]);
            acc[0][1] = fmaf(a0, b.y, acc[0][1]);
            acc[0][2] = fmaf(a0, b.z, acc[0][2]);
            acc[0][3] = fmaf(a0, b.w, acc[0][3]);
            acc[1][0] = fmaf(a1, b.x, acc[1][0]);
            acc[1][1] = fmaf(a1, b.y, acc[1][1]);
            acc[1][2] = fmaf(a1, b.z, acc[1][2]);
            acc[1][3] = fmaf(a1, b.w, acc[1][3]);
            acc[2][0] = fmaf(a2, b.x, acc[2][0]);
            acc[2][1] = fmaf(a2, b.y, acc[2][1]);
            acc[2][2] = fmaf(a2, b.z, acc[2][2]);
            acc[2][3] = fmaf(a2, b.w, acc[2][3]);
            acc[3][0] = fmaf(a3, b.x, acc[3][0]);
            acc[3][1] = fmaf(a3, b.y, acc[3][1]);
            acc[3][2] = fmaf(a3, b.z, acc[3][2]);
            acc[3][3] = fmaf(a3, b.w, acc[3][3]);
        }
    }

    int ggl = bg * 64 + g0;
    float4 bi = *(const float4*)(bih_p + ggl);
    float4 bh = *(const float4*)(bhh_p + ggl);
#pragma unroll
    for (int l = 0; l < 4; l++) {
        float4 o;
        o.x = acc[l][0] + bi.x + bh.x;
        o.y = acc[l][1] + bi.y + bh.y;
        o.z = acc[l][2] + bi.z + bh.z;
        o.w = acc[l][3] + bi.w + bh.w;
        *(float4*)(g_xg + (size_t)(bn * 64 + n0 + l) * G_P + ggl) = o;
    }
}

// ---------------------------------------------------------------------------
// Word LSTM: 8-CTA cluster, packed f32x2 matvec, st.async.b64 h-broadcast.
// Warp w: gate q=w&3, k-slice ks=w>>2; lane = unit within CTA.
// CTA r owns hidden units [r*32, r*32+32). Tail in warp 15 (hi-wid priority).
// Matvec warps decoupled from tail via named barrier 1 (arrive/sync).
// ---------------------------------------------------------------------------
__device__ __forceinline__ uint32_t cluster_rank_() {
    uint32_t r;
    asm("mov.u32 %0, %%cluster_ctarank;" : "=r"(r));
    return r;
}
__device__ __forceinline__ void cluster_sync_() {
    asm volatile("barrier.cluster.arrive.aligned;" ::: "memory");
    asm volatile("barrier.cluster.wait.aligned;" ::: "memory");
}
__device__ __forceinline__ uint32_t mapa_u32(uint32_t la, int r) {
    uint32_t ra;
    asm("mapa.shared::cluster.u32 %0, %1, %2;" : "=r"(ra) : "r"(la), "r"(r));
    return ra;
}
__device__ __forceinline__ void mbar_init_(uint32_t bar, uint32_t cnt) {
    asm volatile("mbarrier.init.shared.b64 [%0], %1;" :: "r"(bar), "r"(cnt) : "memory");
}
__device__ __forceinline__ void mbar_arrive_expect_(uint32_t bar, uint32_t bytes) {
    asm volatile("mbarrier.arrive.expect_tx.shared.b64 _, [%0], %1;"
                 :: "r"(bar), "r"(bytes) : "memory");
}
__device__ __forceinline__ void mbar_wait_parity_(uint32_t bar, uint32_t ph) {
    asm volatile(
        "{\n\t"
        ".reg .pred P1;\n\t"
        "WL_%=:\n\t"
        "mbarrier.try_wait.parity.acquire.cluster.shared::cta.b64 P1, [%0], %1, 0x989680;\n\t"
        "@P1 bra.uni WD_%=;\n\t"
        "bra.uni WL_%=;\n\t"
        "WD_%=:\n\t"
        "}"
        :: "r"(bar), "r"(ph) : "memory");
}
__device__ __forceinline__ void st_async_b64_(uint32_t raddr, unsigned long long v,
                                              uint32_t rbar) {
    asm volatile(
        "st.async.shared::cluster.mbarrier::complete_tx::bytes.b64 [%0], %1, [%2];"
        :: "r"(raddr), "l"(v), "r"(rbar) : "memory");
}

__global__ void __launch_bounds__(512, 1) __cluster_dims__(8, 1, 1)
word_lstm_kernel(const float* __restrict__ Whh_p) {
    __shared__ __align__(16) float hbuf[2][HP];     // h double-buffer (per-CTA replica)
    __shared__ __align__(16) float pacc[2][512];    // partials, parity-buffered
    __shared__ __align__(8) unsigned long long hbar[2];

    int rank = (int)cluster_rank_();
    int tid = threadIdx.x;
    int w = tid >> 5, lane = tid & 31;
    int q = w & 3;                        // gate quadrant
    int ks = w >> 2;                      // k-slice 0..3
    int grow = q * HP + rank * 32 + lane; // global gate row 0..1023

    // resident packed weights: Whh_p[grow][ks*64 .. ks*64+64) as 32 f32x2
    unsigned long long wreg[32];
    {
        const float* wp = Whh_p + (size_t)grow * HP + ks * 64;
#pragma unroll
        for (int i = 0; i < 16; i++) {
            ulonglong2 v = *(const ulonglong2*)(wp + i * 4);
            wreg[2 * i] = v.x;
            wreg[2 * i + 1] = v.y;
        }
    }

    ((float*)hbuf)[tid] = 0.0f;           // 512 floats = both buffers
    uint32_t bar0 = (uint32_t)__cvta_generic_to_shared(&hbar[0]);
    uint32_t hb0  = (uint32_t)__cvta_generic_to_shared(&hbuf[0][0]);
    if (tid == 0) { mbar_init_(bar0, 1); mbar_init_(bar0 + 8, 1); }

    // hoisted remote addresses (barrier[0] and hbuf[0] bases per peer)
    uint32_t rd_h[8], rd_b[8];
#pragma unroll
    for (int r = 0; r < 8; r++) {
        rd_h[r] = mapa_u32(hb0, r);
        rd_b[r] = mapa_u32(bar0, r);
    }

    bool tail = (w == 15);
    float c = 0.0f;
    // x pipeline: xc = step n, xp = step n+1; prefetch issues for n+2.
    float xc0 = 0.f, xc1 = 0.f, xc2 = 0.f, xc3 = 0.f;
    float xp0 = 0.f, xp1 = 0.f, xp2 = 0.f, xp3 = 0.f;
    if (tail) {
        const float* xa = g_xg + rank * 32 + lane;
        xc0 = __ldg(xa);
        xc1 = __ldg(xa + HP);
        xc2 = __ldg(xa + 2 * HP);
        xc3 = __ldg(xa + 3 * HP);
        const float* xb = g_xg + (size_t)G_P + rank * 32 + lane;
        xp0 = __ldg(xb);
        xp1 = __ldg(xb + HP);
        xp2 = __ldg(xb + 2 * HP);
        xp3 = __ldg(xb + 3 * HP);
    }
    __syncthreads();
    cluster_sync_();   // barriers + hbuf init visible cluster-wide

    for (int n = 0; n < NWORDS; n++) {
        int p = n & 1;
        if (n > 0)   // wait for h_n delivery (completion n-1 on barrier[(n-1)&1])
            mbar_wait_parity_(bar0 + ((n - 1) & 1) * 8, (uint32_t)(((n - 1) >> 1) & 1));
        if (tid == 0 && n < NWORDS - 1)
            mbar_arrive_expect_(bar0 + p * 8, 1024u);   // 128 msgs * 8B

        // issue prefetch for step n+2 (tail warp; ~2 steps of latency cover)
        float xn0 = 0.f, xn1 = 0.f, xn2 = 0.f, xn3 = 0.f;
        if (tail && n + 2 < NWORDS) {
            const float* xq = g_xg + (size_t)(n + 2) * G_P + rank * 32 + lane;
            xn0 = __ldg(xq);
            xn1 = __ldg(xq + HP);
            xn2 = __ldg(xq + 2 * HP);
            xn3 = __ldg(xq + 3 * HP);
        }

        // packed matvec slice: lane-uniform smem reads (broadcast)
        const ulonglong2* hp2 = (const ulonglong2*)(&hbuf[p][ks * 64]);
        unsigned long long a0 = 0ull, a1 = 0ull;
#pragma unroll
        for (int i = 0; i < 16; i++) {
            ulonglong2 hv = hp2[i];
            FMA_F32X2(a0, wreg[2 * i], hv.x);
            FMA_F32X2(a1, wreg[2 * i + 1], hv.y);
        }
        {
            float l0, h0, l1, h1;
            UNPACK_F32X2(l0, h0, a0);
            UNPACK_F32X2(l1, h1, a1);
            pacc[p][tid] = (l0 + h0) + (l1 + h1);
        }

        if (!tail) {
            // producers: hand off and go straight to next step's mbarrier wait
            asm volatile("bar.arrive 1, 512;" ::: "memory");
        } else {
            asm volatile("bar.sync 1, 512;" ::: "memory");
            // lane = unit; gather 4 k-slices per gate (bank = lane, conflict-free)
            const float* pb = &pacc[p][0];
            float s0 = 0.f, s1 = 0.f, s2 = 0.f, s3 = 0.f;
#pragma unroll
            for (int k2 = 0; k2 < 4; k2++) {
                int base = k2 * 128 + lane;
                s0 += pb[base];
                s1 += pb[base + 32];
                s2 += pb[base + 64];
                s3 += pb[base + 96];
            }
            float iv = sigf(s0 + xc0);
            float fv = sigf(s1 + xc1);
            float gv = tanhfast(s2 + xc2);
            float ov = sigf(s3 + xc3);
            c = fmaf(fv, c, iv * gv);
            float hn = ov * tanhfast(c);
            g_hs[(size_t)n * HP + rank * 32 + lane] = hn;

            if (n < NWORDS - 1) {
                // pair lanes -> 8B payloads; even lanes send (128 msgs/step total)
                float pv = __shfl_xor_sync(0xffffffffu, hn, 1);
                if ((lane & 1) == 0) {
                    unsigned long long hv2;
                    asm("mov.b64 %0, {%1, %2};" : "=l"(hv2) : "f"(hn), "f"(pv));
                    uint32_t off = (uint32_t)((p ^ 1) * (HP * 4) + (rank * 32 + lane) * 4);
                    uint32_t boff = (uint32_t)(p * 8);
#pragma unroll
                    for (int r = 0; r < 8; r++)
                        st_async_b64_(rd_h[r] + off, hv2, rd_b[r] + boff);
                }
            }
            xc0 = xp0; xc1 = xp1; xc2 = xp2; xc3 = xp3;
            xp0 = xn0; xp1 = xn1; xp2 = xn2; xp3 = xn3;
        }
    }
    cluster_sync_();   // no CTA exits while peers' st.async may be in flight
}

// ---------------------------------------------------------------------------
// Tag projection + log-softmax: one block (64 threads) per word
// ---------------------------------------------------------------------------
__global__ void __launch_bounds__(64)
tag_kernel(const float* __restrict__ W_tag,
           const float* __restrict__ b_tag,
           float* __restrict__ out) {
    __shared__ float hs[HP];
    __shared__ float vals[TAGS];
    __shared__ float red[2];

    int n = blockIdx.x;
    int t = threadIdx.x;
    *(float4*)(hs + t * 4) = *(const float4*)(g_hs + (size_t)n * HP + t * 4);
    __syncthreads();

    if (t < TAGS) {
        const float* wr = W_tag + t * HP;
        float a0 = b_tag[t], a1 = 0.0f, a2 = 0.0f, a3 = 0.0f;
#pragma unroll 8
        for (int k = 0; k < HP; k += 4) {
            float4 wv = *(const float4*)(wr + k);
            a0 = fmaf(wv.x, hs[k + 0], a0);
            a1 = fmaf(wv.y, hs[k + 1], a1);
            a2 = fmaf(wv.z, hs[k + 2], a2);
            a3 = fmaf(wv.w, hs[k + 3], a3);
        }
        vals[t] = (a0 + a1) + (a2 + a3);
    }
    __syncthreads();

    if (t < 32) {
        float m = vals[t];
        if (t + 32 < TAGS) m = fmaxf(m, vals[t + 32]);
#pragma unroll
        for (int o = 16; o > 0; o >>= 1)
            m = fmaxf(m, __shfl_xor_sync(0xffffffffu, m, o));
        float s = expf(vals[t] - m);
        if (t + 32 < TAGS) s += expf(vals[t + 32] - m);
#pragma unroll
        for (int o = 16; o > 0; o >>= 1)
            s += __shfl_xor_sync(0xffffffffu, s, o);
        if (t == 0) { red[0] = m; red[1] = logf(s); }
    }
    __syncthreads();

    if (t < TAGS) out[(size_t)n * TAGS + t] = vals[t] - red[0] - red[1];
}

// ---------------------------------------------------------------------------
// Launch
// ---------------------------------------------------------------------------
extern "C" void kernel_launch(void* const* d_in, const int* in_sizes, int n_in,
                              void* d_out, int out_size) {
    const float* char_emb = (const float*)d_in[0];
    const float* word_emb = (const float*)d_in[1];
    const float* Wih_e    = (const float*)d_in[2];
    const float* Whh_e    = (const float*)d_in[3];
    const float* bih_e    = (const float*)d_in[4];
    const float* bhh_e    = (const float*)d_in[5];
    const float* Wih_p    = (const float*)d_in[6];
    const float* Whh_p    = (const float*)d_in[7];
    const float* bih_p    = (const float*)d_in[8];
    const float* bhh_p    = (const float*)d_in[9];
    const float* W_tag    = (const float*)d_in[10];
    const float* b_tag    = (const float*)d_in[11];
    const int*   sentence = (const int*)d_in[12];
    const int*   char_ids = (const int*)d_in[13];
    const int*   char_len = (const int*)d_in[14];
    float* out = (float*)d_out;

    (void)in_sizes; (void)n_in; (void)out_size;

    cudaFuncSetAttribute(char_lstm_kernel,
                         cudaFuncAttributeMaxDynamicSharedMemorySize,
                         CHAR_SMEM_BYTES);

    prep_table_kernel<<<256, 256>>>(char_emb, Wih_e, bih_e, bhh_e);
    prep_wte_kernel<<<256, 256>>>(Whh_e);
    prep_wpt_kernel<<<1536, 256>>>(Wih_p);

    char_lstm_kernel<<<128, 256, CHAR_SMEM_BYTES>>>(char_ids, char_len);

    xgates_kernel<<<dim3(16, 128), 256>>>(word_emb, sentence, bih_p, bhh_p);

    word_lstm_kernel<<<8, 512>>>(Whh_p);

    tag_kernel<<<NWORDS, 64>>>(W_tag, b_tag, out);
}